// round 2
// baseline (speedup 1.0000x reference)
#include <cuda_runtime.h>
#include <cuda_bf16.h>
#include <mma.h>

using namespace nvcuda;

// ---------------- problem constants ----------------
#define BATCH   16
#define DIM     256
#define HEADS   8
#define DHEAD   32
#define INNER   256
#define NPIX    4096
#define SCALE   0.17677669529663687f
#define EPS     1e-5f

// ---------------- scratch ----------------
__device__ float g_xn  [(size_t)BATCH * DIM * NPIX];    // LN(x) tf32-rounded; later attn out
__device__ float g_b1  [(size_t)BATCH * 768 * NPIX];    // qkv after 1x1; later y
__device__ float g_b2  [(size_t)BATCH * 768 * NPIX];    // qkv after dwconv (+softmaxes)
__device__ float g_ctx [(size_t)BATCH * HEADS * DHEAD * DHEAD];
__device__ float g_wqkv[768 * 256];                     // stacked tf32-rounded weights
__device__ float g_wo2 [256 * 256];

__device__ __forceinline__ float tf32r(float x) {
    float y;
    asm("cvt.rna.tf32.f32 %0, %1;" : "=f"(y) : "f"(x));
    return y;
}

__device__ __forceinline__ void cp16(void* dst, const void* src) {
    unsigned d = (unsigned)__cvta_generic_to_shared(dst);
    asm volatile("cp.async.cg.shared.global [%0], [%1], 16;\n" :: "r"(d), "l"(src));
}

// =====================================================================
// 0. round weights to tf32, stack qkv
// =====================================================================
__global__ __launch_bounds__(256)
void round_weights(const float* __restrict__ wq, const float* __restrict__ wk,
                   const float* __restrict__ wv, const float* __restrict__ wo)
{
    int i = blockIdx.x * 256 + threadIdx.x;       // 768 blocks -> 196608
    if (i < 65536) {
        g_wqkv[i] = tf32r(wq[i]);
        g_wo2[i]  = tf32r(wo[i]);
    } else if (i < 131072) {
        g_wqkv[i] = tf32r(wk[i - 65536]);
    } else {
        g_wqkv[i] = tf32r(wv[i - 131072]);
    }
}

// =====================================================================
// 1/9, 9/9. channel LayerNorm (optionally round output to tf32)
// =====================================================================
__global__ __launch_bounds__(256)
void ln_kernel(const float* __restrict__ in, const float* __restrict__ g,
               float* __restrict__ out, int rnd)
{
    int idx = blockIdx.x * 256 + threadIdx.x;
    int b = idx >> 12, p = idx & 4095;
    const float* base = in  + (size_t)b * DIM * NPIX + p;
    float*       ob   = out + (size_t)b * DIM * NPIX + p;

    float s = 0.f, ss = 0.f;
#pragma unroll 8
    for (int c = 0; c < DIM; c++) {
        float v = base[(size_t)c * NPIX];
        s += v; ss += v * v;
    }
    float mean = s * (1.f / DIM);
    float var  = ss * (1.f / DIM) - mean * mean;
    float rstd = rsqrtf(var + EPS);
    if (rnd) {
#pragma unroll 8
        for (int c = 0; c < DIM; c++)
            ob[(size_t)c * NPIX] = tf32r((base[(size_t)c * NPIX] - mean) * rstd * g[c]);
    } else {
#pragma unroll 8
        for (int c = 0; c < DIM; c++)
            ob[(size_t)c * NPIX] = (base[(size_t)c * NPIX] - mean) * rstd * g[c];
    }
}

// =====================================================================
// tf32 GEMM, cp.async double buffered.
//   C[z, m, n] = sum_k A[m,k] * B[z,k,n];  A: [M,256] rm (tf32 vals),
//   B: [z][256][4096] (tf32 vals). Tile 128x128x32, 512 thr (16 warps 4x4).
// =====================================================================
#define BM 128
#define BN 128
#define BK 32
#define GEMM_SMEM ((2*BM*(BK+4) + 2*BK*(BN+4)) * 4)

__global__ __launch_bounds__(512)
void gemm_tf32(const float* __restrict__ A, const float* __restrict__ B,
               float* __restrict__ C, long strideB, long strideC)
{
    extern __shared__ float smbuf[];
    typedef float AsT[BM][BK + 4];
    typedef float BsT[BK][BN + 4];
    AsT* As = (AsT*)smbuf;                              // As[2]
    BsT* Bs = (BsT*)(smbuf + 2 * BM * (BK + 4));        // Bs[2]

    const int tid = threadIdx.x;
    const int bm = blockIdx.y * BM;
    const int bn = blockIdx.x * BN;

    const float* Bb = B + (size_t)blockIdx.z * strideB;
    float*       Cb = C + (size_t)blockIdx.z * strideC;

    const int warp = tid >> 5;
    const int wm = (warp >> 2) * 32;
    const int wn = (warp & 3) * 32;

    const int arow = tid >> 3;            // 0..63
    const int acol = (tid & 7) * 4;
    const int brow = tid >> 5;            // 0..15
    const int bcol = (tid & 31) * 4;

    const float* Ab0 = &A[(size_t)(bm + arow) * 256 + acol];
    const float* Ab1 = &A[(size_t)(bm + arow + 64) * 256 + acol];
    const float* Bb0 = &Bb[(size_t)brow * NPIX + bn + bcol];
    const float* Bb1 = &Bb[(size_t)(brow + 16) * NPIX + bn + bcol];

    wmma::fragment<wmma::accumulator, 16, 16, 8, float> acc[2][2];
#pragma unroll
    for (int i = 0; i < 2; i++)
#pragma unroll
        for (int j = 0; j < 2; j++) wmma::fill_fragment(acc[i][j], 0.f);

    // prologue: tile 0
    {
        cp16(&As[0][arow][acol],      Ab0);
        cp16(&As[0][arow + 64][acol], Ab1);
        cp16(&Bs[0][brow][bcol],      Bb0);
        cp16(&Bs[0][brow + 16][bcol], Bb1);
        asm volatile("cp.async.commit_group;\n");
    }

    int buf = 0;
#pragma unroll 1
    for (int t = 0; t < 8; t++) {
        asm volatile("cp.async.wait_group 0;\n");
        __syncthreads();
        if (t < 7) {
            int kt = (t + 1) * BK;
            cp16(&As[buf ^ 1][arow][acol],      Ab0 + kt);
            cp16(&As[buf ^ 1][arow + 64][acol], Ab1 + kt);
            cp16(&Bs[buf ^ 1][brow][bcol],      Bb0 + (size_t)kt * NPIX);
            cp16(&Bs[buf ^ 1][brow + 16][bcol], Bb1 + (size_t)kt * NPIX);
            asm volatile("cp.async.commit_group;\n");
        }
#pragma unroll
        for (int kk = 0; kk < BK; kk += 8) {
            wmma::fragment<wmma::matrix_a, 16, 16, 8, wmma::precision::tf32, wmma::row_major> af[2];
            wmma::fragment<wmma::matrix_b, 16, 16, 8, wmma::precision::tf32, wmma::row_major> bf[2];
#pragma unroll
            for (int i = 0; i < 2; i++)
                wmma::load_matrix_sync(af[i], &As[buf][wm + i * 16][kk], BK + 4);
#pragma unroll
            for (int j = 0; j < 2; j++)
                wmma::load_matrix_sync(bf[j], &Bs[buf][kk][wn + j * 16], BN + 4);
#pragma unroll
            for (int i = 0; i < 2; i++)
#pragma unroll
                for (int j = 0; j < 2; j++)
                    wmma::mma_sync(acc[i][j], af[i], bf[j], acc[i][j]);
        }
        buf ^= 1;
    }

#pragma unroll
    for (int i = 0; i < 2; i++)
#pragma unroll
        for (int j = 0; j < 2; j++) {
            float* cp = Cb + (size_t)(bm + wm + i * 16) * NPIX + bn + wn + j * 16;
            wmma::store_matrix_sync(cp, acc[i][j], NPIX, wmma::mem_row_major);
        }
}

// =====================================================================
// 3a. fused dwconv3x3 + feature-softmax for q (channels 0-255).
//   one block per (b, head, 16x16 spatial tile)
// =====================================================================
__global__ __launch_bounds__(256)
void dwconv_softmax_q(const float* __restrict__ in, const float* __restrict__ w,
                      float* __restrict__ out)
{
    __shared__ float s[32][324];      // 18x18 halo tiles, 32 channels
    __shared__ float wsm[32][9];

    int blk = blockIdx.x;             // b*128 + h*16 + t
    int t = blk & 15;
    int h = (blk >> 4) & 7;
    int b = blk >> 7;
    int x0 = (t >> 2) * 16, y0 = (t & 3) * 16;

    const float* ip = in + ((size_t)b * 768 + h * 32) * NPIX;

    for (int i = threadIdx.x; i < 288; i += 256)
        wsm[i / 9][i % 9] = w[h * 288 + i];

    for (int i = threadIdx.x; i < 32 * 324; i += 256) {
        int ch = i / 324;
        int idx = i - ch * 324;
        int r = idx / 18, c = idx - r * 18;
        int gx = x0 + r - 1, gy = y0 + c - 1;
        float v = 0.f;
        if (gx >= 0 && gx < 64 && gy >= 0 && gy < 64)
            v = ip[(size_t)ch * NPIX + gx * 64 + gy];
        s[ch][idx] = v;
    }
    __syncthreads();

    int px = threadIdx.x >> 4, py = threadIdx.x & 15;
    float v[32];
    float m = -1e30f;
#pragma unroll
    for (int ch = 0; ch < 32; ch++) {
        const float* c0 = &s[ch][px * 18 + py];
        float r = c0[0]  * wsm[ch][0] + c0[1]  * wsm[ch][1] + c0[2]  * wsm[ch][2]
                + c0[18] * wsm[ch][3] + c0[19] * wsm[ch][4] + c0[20] * wsm[ch][5]
                + c0[36] * wsm[ch][6] + c0[37] * wsm[ch][7] + c0[38] * wsm[ch][8];
        v[ch] = r;
        m = fmaxf(m, r);
    }
    float ssum = 0.f;
#pragma unroll
    for (int ch = 0; ch < 32; ch++) { v[ch] = __expf(v[ch] - m); ssum += v[ch]; }
    float inv = SCALE / ssum;

    float* op = out + ((size_t)b * 768 + h * 32) * NPIX + (x0 + px) * 64 + (y0 + py);
#pragma unroll
    for (int ch = 0; ch < 32; ch++)
        op[(size_t)ch * NPIX] = v[ch] * inv;
}

// =====================================================================
// 3b. depthwise 3x3 for k,v (channels 256-767)
// =====================================================================
__global__ __launch_bounds__(256)
void dwconv_kv(const float* __restrict__ in, const float* __restrict__ wk,
               const float* __restrict__ wv, float* __restrict__ out)
{
    __shared__ float s[66 * 66];
    int bc = blockIdx.x;              // b*512 + ch
    int b = bc >> 9;
    int ch = bc & 511;
    const float* w9 = (ch < 256) ? wk + ch * 9 : wv + (ch - 256) * 9;
    float w0 = w9[0], w1 = w9[1], w2 = w9[2], w3 = w9[3], w4 = w9[4],
          w5 = w9[5], w6 = w9[6], w7 = w9[7], w8 = w9[8];

    const float* ip = in  + ((size_t)b * 768 + 256 + ch) * NPIX;
    float*       op = out + ((size_t)b * 768 + 256 + ch) * NPIX;

    for (int i = threadIdx.x; i < 66 * 66; i += 256) s[i] = 0.f;
    __syncthreads();
    for (int i = threadIdx.x; i < NPIX; i += 256) {
        int x = i >> 6, y = i & 63;
        s[(x + 1) * 66 + y + 1] = ip[i];
    }
    __syncthreads();
    for (int i = threadIdx.x; i < NPIX; i += 256) {
        int x = i >> 6, y = i & 63;
        const float* c = &s[(x + 1) * 66 + (y + 1)];
        op[i] = c[-67] * w0 + c[-66] * w1 + c[-65] * w2
              + c[-1]  * w3 + c[0]   * w4 + c[1]   * w5
              + c[65]  * w6 + c[66]  * w7 + c[67]  * w8;
    }
}

// =====================================================================
// 5. k softmax over sequence (4096) per (b, chan)
// =====================================================================
__global__ __launch_bounds__(256)
void softmax_k_kernel(float* __restrict__ kbuf)
{
    __shared__ float sh[8];
    int b = blockIdx.x >> 8;
    int c = blockIdx.x & 255;
    float* row = kbuf + ((size_t)b * 768 + 256 + c) * NPIX;
    int tid = threadIdx.x;

    float v[16];
    float m = -1e30f;
#pragma unroll
    for (int i = 0; i < 16; i++) { v[i] = row[tid + i * 256]; m = fmaxf(m, v[i]); }
#pragma unroll
    for (int o = 16; o; o >>= 1) m = fmaxf(m, __shfl_xor_sync(~0u, m, o));
    if ((tid & 31) == 0) sh[tid >> 5] = m;
    __syncthreads();
    m = sh[0];
#pragma unroll
    for (int w = 1; w < 8; w++) m = fmaxf(m, sh[w]);

    float s = 0.f;
#pragma unroll
    for (int i = 0; i < 16; i++) { v[i] = __expf(v[i] - m); s += v[i]; }
#pragma unroll
    for (int o = 16; o; o >>= 1) s += __shfl_xor_sync(~0u, s, o);
    __syncthreads();
    if ((tid & 31) == 0) sh[tid >> 5] = s;
    __syncthreads();
    s = 0.f;
#pragma unroll
    for (int w = 0; w < 8; w++) s += sh[w];

    float inv = 1.f / s;
#pragma unroll
    for (int i = 0; i < 16; i++) row[tid + i * 256] = v[i] * inv;
}

// =====================================================================
// 6. ctx[b,h,d,e] = sum_p k[b,h,p,d] * v[b,h,p,e]
// =====================================================================
__global__ __launch_bounds__(256)
void ctx_kernel(const float* __restrict__ b2, float* __restrict__ ctx)
{
    __shared__ float sh[8448];
    float* ksT = sh;
    float* vsT = sh + 4224;

    int bh = blockIdx.x;
    int b = bh >> 3, h = bh & 7;
    const float* kb = b2 + ((size_t)b * 768 + 256 + h * DHEAD) * NPIX;
    const float* vb = b2 + ((size_t)b * 768 + 512 + h * DHEAD) * NPIX;

    int tid = threadIdx.x;
    int pg = tid >> 6;
    int t  = tid & 63;
    int d0 = (t >> 3) * 4;
    int e0 = (t & 7) * 4;

    float acc[16];
#pragma unroll
    for (int i = 0; i < 16; i++) acc[i] = 0.f;

    for (int c0 = 0; c0 < NPIX; c0 += 128) {
        __syncthreads();
        for (int i = tid; i < 4096; i += 256) {
            int d = i >> 7, p = i & 127;
            ksT[p * 33 + d] = kb[(size_t)d * NPIX + c0 + p];
            vsT[p * 33 + d] = vb[(size_t)d * NPIX + c0 + p];
        }
        __syncthreads();
        int pbeg = pg * 32;
#pragma unroll 4
        for (int pp = pbeg; pp < pbeg + 32; pp++) {
            float kk[4], vv[4];
#pragma unroll
            for (int i = 0; i < 4; i++) kk[i] = ksT[pp * 33 + d0 + i];
#pragma unroll
            for (int j = 0; j < 4; j++) vv[j] = vsT[pp * 33 + e0 + j];
#pragma unroll
            for (int i = 0; i < 4; i++)
#pragma unroll
                for (int j = 0; j < 4; j++) acc[i * 4 + j] += kk[i] * vv[j];
        }
    }
    __syncthreads();

    float* red = sh;
#pragma unroll
    for (int i = 0; i < 4; i++)
#pragma unroll
        for (int j = 0; j < 4; j++)
            red[pg * 1024 + (d0 + i) * 32 + (e0 + j)] = acc[i * 4 + j];
    __syncthreads();

    float* cout = ctx + (size_t)bh * 1024;
    for (int i = tid; i < 1024; i += 256)
        cout[i] = red[i] + red[1024 + i] + red[2048 + i] + red[3072 + i];
}

// =====================================================================
// 7. out = silu(q @ ctx), rounded to tf32 (feeds wo GEMM)
// =====================================================================
__global__ __launch_bounds__(256)
void attn_out_kernel(const float* __restrict__ qbuf, const float* __restrict__ ctx,
                     float* __restrict__ out)
{
    __shared__ float cs[DHEAD][DHEAD + 1];
    int blk = blockIdx.x;
    int pt = blk & 15;
    int bh = blk >> 4;
    int b = bh >> 3, h = bh & 7;

    const float* cbase = ctx + (size_t)bh * 1024;
    for (int i = threadIdx.x; i < 1024; i += 256)
        cs[i >> 5][i & 31] = cbase[i];
    __syncthreads();

    int p = pt * 256 + threadIdx.x;
    const float* qb = qbuf + ((size_t)b * 768 + h * DHEAD) * NPIX + p;

    float qv[DHEAD];
#pragma unroll
    for (int d = 0; d < DHEAD; d++) qv[d] = qb[(size_t)d * NPIX];

    float o[DHEAD];
#pragma unroll
    for (int e = 0; e < DHEAD; e++) o[e] = 0.f;

#pragma unroll 8
    for (int d = 0; d < DHEAD; d++) {
        float qd = qv[d];
#pragma unroll
        for (int e = 0; e < DHEAD; e++) o[e] += qd * cs[d][e];
    }

    float* ob = out + ((size_t)b * DIM + h * DHEAD) * NPIX + p;
#pragma unroll
    for (int e = 0; e < DHEAD; e++) {
        float x = o[e];
        ob[(size_t)e * NPIX] = tf32r(x / (1.f + __expf(-x)));
    }
}

// =====================================================================
// launch
// =====================================================================
extern "C" void kernel_launch(void* const* d_in, const int* in_sizes, int n_in,
                              void* d_out, int out_size)
{
    const float* fmap   = (const float*)d_in[0];
    const float* gn     = (const float*)d_in[1];
    const float* wq1    = (const float*)d_in[2];
    const float* wq_dw  = (const float*)d_in[3];
    const float* wk1    = (const float*)d_in[4];
    const float* wk_dw  = (const float*)d_in[5];
    const float* wv1    = (const float*)d_in[6];
    const float* wv_dw  = (const float*)d_in[7];
    const float* wo     = (const float*)d_in[8];
    const float* gout   = (const float*)d_in[9];
    float* out = (float*)d_out;

    float *xn, *b1, *b2, *ctxb, *wqkv, *wo2;
    cudaGetSymbolAddress((void**)&xn,   g_xn);
    cudaGetSymbolAddress((void**)&b1,   g_b1);
    cudaGetSymbolAddress((void**)&b2,   g_b2);
    cudaGetSymbolAddress((void**)&ctxb, g_ctx);
    cudaGetSymbolAddress((void**)&wqkv, g_wqkv);
    cudaGetSymbolAddress((void**)&wo2,  g_wo2);

    cudaFuncSetAttribute(gemm_tf32, cudaFuncAttributeMaxDynamicSharedMemorySize, GEMM_SMEM);

    // 0. weights -> tf32 stacked
    round_weights<<<768, 256>>>(wq1, wk1, wv1, wo);

    // 1. channel LN (tf32-rounded output)
    ln_kernel<<<256, 256>>>(fmap, gn, xn, 1);

    // 2. fused QKV 1x1 conv GEMM
    dim3 gq(NPIX / BN, 768 / BM, BATCH);
    gemm_tf32<<<gq, 512, GEMM_SMEM>>>(wqkv, xn, b1, 256L * NPIX, 768L * NPIX);

    // 3. dwconv (+ fused q softmax)
    dwconv_softmax_q<<<BATCH * HEADS * 16, 256>>>(b1, wq_dw, b2);
    dwconv_kv<<<BATCH * 512, 256>>>(b1, wk_dw, wv_dw, b2);

    // 5. k softmax over sequence
    softmax_k_kernel<<<4096, 256>>>(b2);

    // 6. ctx = k^T v
    ctx_kernel<<<BATCH * HEADS, 256>>>(b2, ctxb);

    // 7. out = silu(q @ ctx) (tf32-rounded)
    attn_out_kernel<<<2048, 256>>>(b2, ctxb, xn);

    // 8. wo 1x1 conv GEMM
    dim3 gw(NPIX / BN, 256 / BM, BATCH);
    gemm_tf32<<<gw, 512, GEMM_SMEM>>>(wo2, xn, b1, 256L * NPIX, 256L * NPIX);

    // 9. final LN
    ln_kernel<<<256, 256>>>(b1, gout, out, 0);
}

// round 4
// speedup vs baseline: 1.6141x; 1.6141x over previous
#include <cuda_runtime.h>
#include <cuda_fp16.h>
#include <mma.h>
#include <cstdint>

using namespace nvcuda;

// ---------------- problem constants ----------------
#define BATCH   16
#define DIM     256
#define HEADS   8
#define DHEAD   32
#define NPIX    4096
#define SCALE   0.17677669529663687f
#define EPS     1e-5f

// ---------------- scratch ----------------
__device__ __half g_xnh [(size_t)BATCH * NPIX * DIM];   // pixel-major fp16: LN out, later attn out
__device__ float  g_b1  [(size_t)BATCH * 768 * NPIX];   // channel-major fp32: qkv after 1x1; later y
__device__ float  g_b2  [(size_t)BATCH * 768 * NPIX];   // qkv after dwconv (+softmaxes)
__device__ float  g_ctx [(size_t)BATCH * HEADS * DHEAD * DHEAD];
__device__ __half g_wqkv[768 * 256];
__device__ __half g_wo2 [256 * 256];

__device__ __forceinline__ void cp16s(void* dst, const void* src) {
    unsigned d = (unsigned)__cvta_generic_to_shared(dst);
    asm volatile("cp.async.cg.shared.global [%0], [%1], 16;\n" :: "r"(d), "l"(src));
}
#define CP_COMMIT()  asm volatile("cp.async.commit_group;\n" ::: "memory")
#define CP_WAIT0()   asm volatile("cp.async.wait_group 0;\n" ::: "memory")

// =====================================================================
// 0. weights -> fp16, stack qkv
// =====================================================================
__global__ __launch_bounds__(256)
void round_weights(const float* __restrict__ wq, const float* __restrict__ wk,
                   const float* __restrict__ wv, const float* __restrict__ wo)
{
    int i = blockIdx.x * 256 + threadIdx.x;     // 768 blocks
    if (i < 65536) {
        g_wqkv[i] = __float2half_rn(wq[i]);
        g_wo2[i]  = __float2half_rn(wo[i]);
    } else if (i < 131072) {
        g_wqkv[i] = __float2half_rn(wk[i - 65536]);
    } else {
        g_wqkv[i] = __float2half_rn(wv[i - 131072]);
    }
}

// =====================================================================
// 1. channel LayerNorm: channel-major fp32 in -> pixel-major fp16 out
// =====================================================================
__global__ __launch_bounds__(256)
void ln_to_pix(const float* __restrict__ in, const float* __restrict__ g,
               __half* __restrict__ out)
{
    int idx = blockIdx.x * 256 + threadIdx.x;
    int b = idx >> 12, p = idx & 4095;
    const float* base = in + (size_t)b * DIM * NPIX + p;

    float s = 0.f, ss = 0.f;
#pragma unroll 8
    for (int c = 0; c < DIM; c++) {
        float v = base[(size_t)c * NPIX];
        s += v; ss += v * v;
    }
    float mean = s * (1.f / DIM);
    float var  = ss * (1.f / DIM) - mean * mean;
    float rstd = rsqrtf(var + EPS);

    __half* orow = out + ((size_t)b * NPIX + p) * DIM;
#pragma unroll 4
    for (int c = 0; c < DIM; c += 8) {
        __half2 h[4];
#pragma unroll
        for (int j = 0; j < 4; j++) {
            float a = (base[(size_t)(c + 2*j)     * NPIX] - mean) * rstd * __ldg(&g[c + 2*j]);
            float bb= (base[(size_t)(c + 2*j + 1) * NPIX] - mean) * rstd * __ldg(&g[c + 2*j + 1]);
            h[j] = __floats2half2_rn(a, bb);
        }
        *reinterpret_cast<uint4*>(orow + c) = *reinterpret_cast<uint4*>(h);
    }
}

// =====================================================================
// fp16 WMMA GEMM:  C[z, m, n] = sum_k A[m,k] * B[z][n][k]
//   A: [Mtot,256] row-major fp16.  B: pixel-major [z][4096][256] fp16.
//   C: channel-major fp32 [z][Mtot][4096].
//   Tile 128x128x32, 512 threads (16 warps, 4x4, 32x32 each), 2-stage cp.async.
// =====================================================================
#define BM 128
#define BN 128
#define BKH 32
#define LDH (BKH + 8)

__global__ __launch_bounds__(512)
void gemm_fp16(const __half* __restrict__ A, const __half* __restrict__ B,
               float* __restrict__ C, long strideB, long strideC)
{
    __shared__ __align__(16) __half As[2][BM][LDH];
    __shared__ __align__(16) __half Bs[2][BN][LDH];

    const int tid = threadIdx.x;
    const int bm = blockIdx.y * BM;
    const int bn = blockIdx.x * BN;
    const __half* Bb = B + (size_t)blockIdx.z * strideB;
    float*        Cb = C + (size_t)blockIdx.z * strideC;

    const int warp = tid >> 5;
    const int wm = (warp >> 2) * 32;
    const int wn = (warp & 3) * 32;

    const int row  = tid >> 2;            // 0..127
    const int col8 = (tid & 3) * 8;       // 0,8,16,24
    const __half* gA = &A[(size_t)(bm + row) * 256 + col8];
    const __half* gB = &Bb[(size_t)(bn + row) * 256 + col8];

    wmma::fragment<wmma::accumulator, 16, 16, 16, float> acc[2][2];
#pragma unroll
    for (int i = 0; i < 2; i++)
#pragma unroll
        for (int j = 0; j < 2; j++) wmma::fill_fragment(acc[i][j], 0.f);

    // prologue
    cp16s(&As[0][row][col8], gA);
    cp16s(&Bs[0][row][col8], gB);
    CP_COMMIT();

    int buf = 0;
#pragma unroll 1
    for (int t = 0; t < 8; t++) {
        CP_WAIT0();
        __syncthreads();
        if (t < 7) {
            int k0 = (t + 1) * BKH;
            cp16s(&As[buf ^ 1][row][col8], gA + k0);
            cp16s(&Bs[buf ^ 1][row][col8], gB + k0);
            CP_COMMIT();
        }
#pragma unroll
        for (int kk = 0; kk < BKH; kk += 16) {
            wmma::fragment<wmma::matrix_a, 16, 16, 16, __half, wmma::row_major> af[2];
            wmma::fragment<wmma::matrix_b, 16, 16, 16, __half, wmma::col_major> bf[2];
#pragma unroll
            for (int i = 0; i < 2; i++)
                wmma::load_matrix_sync(af[i], &As[buf][wm + i * 16][kk], LDH);
#pragma unroll
            for (int j = 0; j < 2; j++)
                wmma::load_matrix_sync(bf[j], &Bs[buf][wn + j * 16][kk], LDH);
#pragma unroll
            for (int i = 0; i < 2; i++)
#pragma unroll
                for (int j = 0; j < 2; j++)
                    wmma::mma_sync(acc[i][j], af[i], bf[j], acc[i][j]);
        }
        buf ^= 1;
    }

#pragma unroll
    for (int i = 0; i < 2; i++)
#pragma unroll
        for (int j = 0; j < 2; j++) {
            float* cp = Cb + (size_t)(bm + wm + i * 16) * NPIX + bn + wn + j * 16;
            wmma::store_matrix_sync(cp, acc[i][j], NPIX, wmma::mem_row_major);
        }
}

// =====================================================================
// 3a. fused dwconv3x3 + feature-softmax for q (channels 0-255)
// =====================================================================
__global__ __launch_bounds__(256)
void dwconv_softmax_q(const float* __restrict__ in, const float* __restrict__ w,
                      float* __restrict__ out)
{
    __shared__ float s[32][324];
    __shared__ float wsm[32][9];

    int blk = blockIdx.x;
    int t = blk & 15;
    int h = (blk >> 4) & 7;
    int b = blk >> 7;
    int x0 = (t >> 2) * 16, y0 = (t & 3) * 16;

    const float* ip = in + ((size_t)b * 768 + h * 32) * NPIX;

    for (int i = threadIdx.x; i < 288; i += 256)
        wsm[i / 9][i % 9] = w[h * 288 + i];

    for (int i = threadIdx.x; i < 32 * 324; i += 256) {
        int ch = i / 324;
        int idx = i - ch * 324;
        int r = idx / 18, c = idx - r * 18;
        int gx = x0 + r - 1, gy = y0 + c - 1;
        float v = 0.f;
        if (gx >= 0 && gx < 64 && gy >= 0 && gy < 64)
            v = ip[(size_t)ch * NPIX + gx * 64 + gy];
        s[ch][idx] = v;
    }
    __syncthreads();

    int px = threadIdx.x >> 4, py = threadIdx.x & 15;
    float v[32];
    float m = -1e30f;
#pragma unroll
    for (int ch = 0; ch < 32; ch++) {
        const float* c0 = &s[ch][px * 18 + py];
        float r = c0[0]  * wsm[ch][0] + c0[1]  * wsm[ch][1] + c0[2]  * wsm[ch][2]
                + c0[18] * wsm[ch][3] + c0[19] * wsm[ch][4] + c0[20] * wsm[ch][5]
                + c0[36] * wsm[ch][6] + c0[37] * wsm[ch][7] + c0[38] * wsm[ch][8];
        v[ch] = r;
        m = fmaxf(m, r);
    }
    float ssum = 0.f;
#pragma unroll
    for (int ch = 0; ch < 32; ch++) { v[ch] = __expf(v[ch] - m); ssum += v[ch]; }
    float inv = SCALE / ssum;

    float* op = out + ((size_t)b * 768 + h * 32) * NPIX + (x0 + px) * 64 + (y0 + py);
#pragma unroll
    for (int ch = 0; ch < 32; ch++)
        op[(size_t)ch * NPIX] = v[ch] * inv;
}

// =====================================================================
// 3b. depthwise 3x3 for k,v + fused sequence-softmax for k channels.
//   one block per (b, ch) with ch in [0,512): 0-255 -> k, 256-511 -> v
// =====================================================================
__global__ __launch_bounds__(256)
void dwconv_kv(const float* __restrict__ in, const float* __restrict__ wk,
               const float* __restrict__ wv, float* __restrict__ out)
{
    __shared__ float s[66 * 66];
    __shared__ float red[8];
    int bc = blockIdx.x;
    int b = bc >> 9;
    int ch = bc & 511;
    bool is_k = ch < 256;
    const float* w9 = is_k ? wk + ch * 9 : wv + (ch - 256) * 9;
    float w0 = w9[0], w1 = w9[1], w2 = w9[2], w3 = w9[3], w4 = w9[4],
          w5 = w9[5], w6 = w9[6], w7 = w9[7], w8 = w9[8];

    const float* ip = in  + ((size_t)b * 768 + 256 + ch) * NPIX;
    float*       op = out + ((size_t)b * 768 + 256 + ch) * NPIX;

    int tid = threadIdx.x;
    for (int i = tid; i < 66 * 66; i += 256) s[i] = 0.f;
    __syncthreads();
    for (int i = tid; i < NPIX; i += 256) {
        int x = i >> 6, y = i & 63;
        s[(x + 1) * 66 + y + 1] = ip[i];
    }
    __syncthreads();

    float r[16];
#pragma unroll
    for (int t = 0; t < 16; t++) {
        int i = tid + t * 256;
        int x = i >> 6, y = i & 63;
        const float* c = &s[(x + 1) * 66 + (y + 1)];
        r[t] = c[-67] * w0 + c[-66] * w1 + c[-65] * w2
             + c[-1]  * w3 + c[0]   * w4 + c[1]   * w5
             + c[65]  * w6 + c[66]  * w7 + c[67]  * w8;
    }

    if (!is_k) {
#pragma unroll
        for (int t = 0; t < 16; t++) op[tid + t * 256] = r[t];
        return;
    }

    // fused softmax over all 4096 conv outputs
    float m = -1e30f;
#pragma unroll
    for (int t = 0; t < 16; t++) m = fmaxf(m, r[t]);
#pragma unroll
    for (int o = 16; o; o >>= 1) m = fmaxf(m, __shfl_xor_sync(~0u, m, o));
    if ((tid & 31) == 0) red[tid >> 5] = m;
    __syncthreads();
    m = red[0];
#pragma unroll
    for (int w = 1; w < 8; w++) m = fmaxf(m, red[w]);

    float ssum = 0.f;
#pragma unroll
    for (int t = 0; t < 16; t++) { r[t] = __expf(r[t] - m); ssum += r[t]; }
#pragma unroll
    for (int o = 16; o; o >>= 1) ssum += __shfl_xor_sync(~0u, ssum, o);
    __syncthreads();
    if ((tid & 31) == 0) red[tid >> 5] = ssum;
    __syncthreads();
    ssum = 0.f;
#pragma unroll
    for (int w = 0; w < 8; w++) ssum += red[w];

    float inv = 1.f / ssum;
#pragma unroll
    for (int t = 0; t < 16; t++) op[tid + t * 256] = r[t] * inv;
}

// =====================================================================
// 6. ctx[b,h,d,e] = sum_p k[b,h,p,d] * v[b,h,p,e]
// =====================================================================
__global__ __launch_bounds__(256)
void ctx_kernel(const float* __restrict__ b2, float* __restrict__ ctx)
{
    __shared__ float sh[8448];
    float* ksT = sh;
    float* vsT = sh + 4224;

    int bh = blockIdx.x;
    int b = bh >> 3, h = bh & 7;
    const float* kb = b2 + ((size_t)b * 768 + 256 + h * DHEAD) * NPIX;
    const float* vb = b2 + ((size_t)b * 768 + 512 + h * DHEAD) * NPIX;

    int tid = threadIdx.x;
    int pg = tid >> 6;
    int t  = tid & 63;
    int d0 = (t >> 3) * 4;
    int e0 = (t & 7) * 4;

    float acc[16];
#pragma unroll
    for (int i = 0; i < 16; i++) acc[i] = 0.f;

    for (int c0 = 0; c0 < NPIX; c0 += 128) {
        __syncthreads();
        for (int i = tid; i < 4096; i += 256) {
            int d = i >> 7, p = i & 127;
            ksT[p * 33 + d] = kb[(size_t)d * NPIX + c0 + p];
            vsT[p * 33 + d] = vb[(size_t)d * NPIX + c0 + p];
        }
        __syncthreads();
        int pbeg = pg * 32;
#pragma unroll 4
        for (int pp = pbeg; pp < pbeg + 32; pp++) {
            float kk[4], vv[4];
#pragma unroll
            for (int i = 0; i < 4; i++) kk[i] = ksT[pp * 33 + d0 + i];
#pragma unroll
            for (int j = 0; j < 4; j++) vv[j] = vsT[pp * 33 + e0 + j];
#pragma unroll
            for (int i = 0; i < 4; i++)
#pragma unroll
                for (int j = 0; j < 4; j++) acc[i * 4 + j] += kk[i] * vv[j];
        }
    }
    __syncthreads();

    float* red = sh;
#pragma unroll
    for (int i = 0; i < 4; i++)
#pragma unroll
        for (int j = 0; j < 4; j++)
            red[pg * 1024 + (d0 + i) * 32 + (e0 + j)] = acc[i * 4 + j];
    __syncthreads();

    float* cout = ctx + (size_t)bh * 1024;
    for (int i = tid; i < 1024; i += 256)
        cout[i] = red[i] + red[1024 + i] + red[2048 + i] + red[3072 + i];
}

// =====================================================================
// 7. out = silu(q @ ctx) -> pixel-major fp16 [b][p][c]
// =====================================================================
__global__ __launch_bounds__(256)
void attn_out_kernel(const float* __restrict__ qbuf, const float* __restrict__ ctx,
                     __half* __restrict__ out)
{
    __shared__ float cs[DHEAD][DHEAD + 1];
    int blk = blockIdx.x;
    int pt = blk & 15;
    int bh = blk >> 4;
    int b = bh >> 3, h = bh & 7;

    const float* cbase = ctx + (size_t)bh * 1024;
    for (int i = threadIdx.x; i < 1024; i += 256)
        cs[i >> 5][i & 31] = cbase[i];
    __syncthreads();

    int p = pt * 256 + threadIdx.x;
    const float* qb = qbuf + ((size_t)b * 768 + h * DHEAD) * NPIX + p;

    float qv[DHEAD];
#pragma unroll
    for (int d = 0; d < DHEAD; d++) qv[d] = qb[(size_t)d * NPIX];

    float o[DHEAD];
#pragma unroll
    for (int e = 0; e < DHEAD; e++) o[e] = 0.f;

#pragma unroll 8
    for (int d = 0; d < DHEAD; d++) {
        float qd = qv[d];
#pragma unroll
        for (int e = 0; e < DHEAD; e++) o[e] += qd * cs[d][e];
    }

    __half* ob = out + ((size_t)b * NPIX + p) * DIM + h * DHEAD;
#pragma unroll
    for (int e8 = 0; e8 < DHEAD; e8 += 8) {
        __half2 hh[4];
#pragma unroll
        for (int j = 0; j < 4; j++) {
            float x0 = o[e8 + 2*j],     s0 = x0 / (1.f + __expf(-x0));
            float x1 = o[e8 + 2*j + 1], s1 = x1 / (1.f + __expf(-x1));
            hh[j] = __floats2half2_rn(s0, s1);
        }
        *reinterpret_cast<uint4*>(ob + e8) = *reinterpret_cast<uint4*>(hh);
    }
}

// =====================================================================
// 9. final channel LayerNorm (channel-major fp32 in/out)
// =====================================================================
__global__ __launch_bounds__(256)
void ln_kernel(const float* __restrict__ in, const float* __restrict__ g,
               float* __restrict__ out)
{
    int idx = blockIdx.x * 256 + threadIdx.x;
    int b = idx >> 12, p = idx & 4095;
    const float* base = in  + (size_t)b * DIM * NPIX + p;
    float*       ob   = out + (size_t)b * DIM * NPIX + p;

    float s = 0.f, ss = 0.f;
#pragma unroll 8
    for (int c = 0; c < DIM; c++) {
        float v = base[(size_t)c * NPIX];
        s += v; ss += v * v;
    }
    float mean = s * (1.f / DIM);
    float var  = ss * (1.f / DIM) - mean * mean;
    float rstd = rsqrtf(var + EPS);
#pragma unroll 8
    for (int c = 0; c < DIM; c++)
        ob[(size_t)c * NPIX] = (base[(size_t)c * NPIX] - mean) * rstd * __ldg(&g[c]);
}

// =====================================================================
// launch
// =====================================================================
extern "C" void kernel_launch(void* const* d_in, const int* in_sizes, int n_in,
                              void* d_out, int out_size)
{
    const float* fmap   = (const float*)d_in[0];
    const float* gn     = (const float*)d_in[1];
    const float* wq1    = (const float*)d_in[2];
    const float* wq_dw  = (const float*)d_in[3];
    const float* wk1    = (const float*)d_in[4];
    const float* wk_dw  = (const float*)d_in[5];
    const float* wv1    = (const float*)d_in[6];
    const float* wv_dw  = (const float*)d_in[7];
    const float* wo     = (const float*)d_in[8];
    const float* gout   = (const float*)d_in[9];
    float* out = (float*)d_out;

    __half *xnh, *wqkv, *wo2;
    float *b1, *b2, *ctxb;
    cudaGetSymbolAddress((void**)&xnh,  g_xnh);
    cudaGetSymbolAddress((void**)&b1,   g_b1);
    cudaGetSymbolAddress((void**)&b2,   g_b2);
    cudaGetSymbolAddress((void**)&ctxb, g_ctx);
    cudaGetSymbolAddress((void**)&wqkv, g_wqkv);
    cudaGetSymbolAddress((void**)&wo2,  g_wo2);

    // 0. weights -> fp16 stacked
    round_weights<<<768, 256>>>(wq1, wk1, wv1, wo);

    // 1. channel LN -> pixel-major fp16
    ln_to_pix<<<256, 256>>>(fmap, gn, xnh);

    // 2. fused QKV 1x1 conv (fp16 WMMA GEMM)
    gemm_fp16<<<dim3(NPIX / BN, 768 / BM, BATCH), 512>>>(
        wqkv, xnh, b1, (long)NPIX * DIM, 768L * NPIX);

    // 3. dwconv (+ fused q feature-softmax, k sequence-softmax)
    dwconv_softmax_q<<<BATCH * HEADS * 16, 256>>>(b1, wq_dw, b2);
    dwconv_kv<<<BATCH * 512, 256>>>(b1, wk_dw, wv_dw, b2);

    // 6. ctx = k^T v
    ctx_kernel<<<BATCH * HEADS, 256>>>(b2, ctxb);

    // 7. out = silu(q @ ctx) -> pixel-major fp16
    attn_out_kernel<<<2048, 256>>>(b2, ctxb, xnh);

    // 8. wo 1x1 conv (fp16 WMMA GEMM)
    gemm_fp16<<<dim3(NPIX / BN, 256 / BM, BATCH), 512>>>(
        wo2, xnh, b1, (long)NPIX * DIM, 256L * NPIX);

    // 9. final LN -> d_out
    ln_kernel<<<256, 256>>>(b1, gout, out);
}

// round 5
// speedup vs baseline: 2.5743x; 1.5949x over previous
#include <cuda_runtime.h>
#include <cuda_fp16.h>
#include <mma.h>
#include <cstdint>

using namespace nvcuda;

// ---------------- problem constants ----------------
#define BATCH   16
#define DIM     256
#define HEADS   8
#define DHEAD   32
#define NPIX    4096
#define SCALE   0.17677669529663687f
#define EPS     1e-5f

// ---------------- scratch ----------------
__device__ __half g_xnh [(size_t)BATCH * NPIX * DIM];   // pixel-major fp16: LN out, later attn out
__device__ float  g_b1  [(size_t)BATCH * 768 * NPIX];   // channel-major fp32: qkv after 1x1
__device__ float  g_b2  [(size_t)BATCH * 768 * NPIX];   // qkv after dwconv (+k softmax)
__device__ float  g_ctxp[(size_t)BATCH * HEADS * 4 * DHEAD * DHEAD];  // 4 pixel-partials
__device__ __half g_wqkv[768 * 256];
__device__ __half g_wo2 [256 * 256];

__device__ __forceinline__ void cp16s(void* dst, const void* src) {
    unsigned d = (unsigned)__cvta_generic_to_shared(dst);
    asm volatile("cp.async.cg.shared.global [%0], [%1], 16;\n" :: "r"(d), "l"(src));
}
#define CP_COMMIT()  asm volatile("cp.async.commit_group;\n" ::: "memory")
#define CP_WAIT0()   asm volatile("cp.async.wait_group 0;\n" ::: "memory")

// =====================================================================
// 0. weights -> fp16, stack qkv
// =====================================================================
__global__ __launch_bounds__(256)
void round_weights(const float* __restrict__ wq, const float* __restrict__ wk,
                   const float* __restrict__ wv, const float* __restrict__ wo)
{
    int i = blockIdx.x * 256 + threadIdx.x;
    if (i < 65536) {
        g_wqkv[i] = __float2half_rn(wq[i]);
        g_wo2[i]  = __float2half_rn(wo[i]);
    } else if (i < 131072) {
        g_wqkv[i] = __float2half_rn(wk[i - 65536]);
    } else {
        g_wqkv[i] = __float2half_rn(wv[i - 131072]);
    }
}

// =====================================================================
// 1. channel LayerNorm: channel-major fp32 in -> pixel-major fp16 out
// =====================================================================
__global__ __launch_bounds__(256)
void ln_to_pix(const float* __restrict__ in, const float* __restrict__ g,
               __half* __restrict__ out)
{
    int idx = blockIdx.x * 256 + threadIdx.x;
    int b = idx >> 12, p = idx & 4095;
    const float* base = in + (size_t)b * DIM * NPIX + p;

    float s = 0.f, ss = 0.f;
#pragma unroll 8
    for (int c = 0; c < DIM; c++) {
        float v = base[(size_t)c * NPIX];
        s += v; ss += v * v;
    }
    float mean = s * (1.f / DIM);
    float var  = ss * (1.f / DIM) - mean * mean;
    float rstd = rsqrtf(var + EPS);

    __half* orow = out + ((size_t)b * NPIX + p) * DIM;
#pragma unroll 4
    for (int c = 0; c < DIM; c += 8) {
        __half2 h[4];
#pragma unroll
        for (int j = 0; j < 4; j++) {
            float a = (base[(size_t)(c + 2*j)     * NPIX] - mean) * rstd * __ldg(&g[c + 2*j]);
            float bb= (base[(size_t)(c + 2*j + 1) * NPIX] - mean) * rstd * __ldg(&g[c + 2*j + 1]);
            h[j] = __floats2half2_rn(a, bb);
        }
        *reinterpret_cast<uint4*>(orow + c) = *reinterpret_cast<uint4*>(h);
    }
}

// =====================================================================
// 2. QKV fp16 WMMA GEMM:  C[z, m, n] = sum_k A[m,k] * B[z][n][k]
//   Tile 128x128x32, 512 threads, 2-stage cp.async. (proven round 4)
// =====================================================================
#define BM 128
#define BN 128
#define BKH 32
#define LDH (BKH + 8)

__global__ __launch_bounds__(512)
void gemm_fp16(const __half* __restrict__ A, const __half* __restrict__ B,
               float* __restrict__ C, long strideB, long strideC)
{
    __shared__ __align__(16) __half As[2][BM][LDH];
    __shared__ __align__(16) __half Bs[2][BN][LDH];

    const int tid = threadIdx.x;
    const int bm = blockIdx.y * BM;
    const int bn = blockIdx.x * BN;
    const __half* Bb = B + (size_t)blockIdx.z * strideB;
    float*        Cb = C + (size_t)blockIdx.z * strideC;

    const int warp = tid >> 5;
    const int wm = (warp >> 2) * 32;
    const int wn = (warp & 3) * 32;

    const int row  = tid >> 2;
    const int col8 = (tid & 3) * 8;
    const __half* gA = &A[(size_t)(bm + row) * 256 + col8];
    const __half* gB = &Bb[(size_t)(bn + row) * 256 + col8];

    wmma::fragment<wmma::accumulator, 16, 16, 16, float> acc[2][2];
#pragma unroll
    for (int i = 0; i < 2; i++)
#pragma unroll
        for (int j = 0; j < 2; j++) wmma::fill_fragment(acc[i][j], 0.f);

    cp16s(&As[0][row][col8], gA);
    cp16s(&Bs[0][row][col8], gB);
    CP_COMMIT();

    int buf = 0;
#pragma unroll 1
    for (int t = 0; t < 8; t++) {
        CP_WAIT0();
        __syncthreads();
        if (t < 7) {
            int k0 = (t + 1) * BKH;
            cp16s(&As[buf ^ 1][row][col8], gA + k0);
            cp16s(&Bs[buf ^ 1][row][col8], gB + k0);
            CP_COMMIT();
        }
#pragma unroll
        for (int kk = 0; kk < BKH; kk += 16) {
            wmma::fragment<wmma::matrix_a, 16, 16, 16, __half, wmma::row_major> af[2];
            wmma::fragment<wmma::matrix_b, 16, 16, 16, __half, wmma::col_major> bf[2];
#pragma unroll
            for (int i = 0; i < 2; i++)
                wmma::load_matrix_sync(af[i], &As[buf][wm + i * 16][kk], LDH);
#pragma unroll
            for (int j = 0; j < 2; j++)
                wmma::load_matrix_sync(bf[j], &Bs[buf][wn + j * 16][kk], LDH);
#pragma unroll
            for (int i = 0; i < 2; i++)
#pragma unroll
                for (int j = 0; j < 2; j++)
                    wmma::mma_sync(acc[i][j], af[i], bf[j], acc[i][j]);
        }
        buf ^= 1;
    }

#pragma unroll
    for (int i = 0; i < 2; i++)
#pragma unroll
        for (int j = 0; j < 2; j++) {
            float* cp = Cb + (size_t)(bm + wm + i * 16) * NPIX + bn + wn + j * 16;
            wmma::store_matrix_sync(cp, acc[i][j], NPIX, wmma::mem_row_major);
        }
}

// =====================================================================
// 3. depthwise 3x3 for ALL 768 channels; k channels (256-511) get
//    fused sequence-softmax. One block per (b, ch).
// =====================================================================
__global__ __launch_bounds__(256)
void dwconv_all(const float* __restrict__ in, const float* __restrict__ wq,
                const float* __restrict__ wk, const float* __restrict__ wv,
                float* __restrict__ out)
{
    __shared__ float s[66 * 66];
    __shared__ float red[8];
    int bc = blockIdx.x;                  // b*768 + ch
    int b = bc / 768;
    int ch = bc - b * 768;
    bool is_k = (ch >= 256) && (ch < 512);
    const float* w9 = (ch < 256) ? wq + ch * 9
                     : (ch < 512) ? wk + (ch - 256) * 9
                                  : wv + (ch - 512) * 9;
    float w0 = w9[0], w1 = w9[1], w2 = w9[2], w3 = w9[3], w4 = w9[4],
          w5 = w9[5], w6 = w9[6], w7 = w9[7], w8 = w9[8];

    const float* ip = in  + (size_t)bc * NPIX;
    float*       op = out + (size_t)bc * NPIX;

    int tid = threadIdx.x;
    // zero halo region only (rows 0,65 and cols 0,65)
    for (int i = tid; i < 66; i += 256) {
        s[i] = 0.f;                 // top row
        s[65 * 66 + i] = 0.f;       // bottom row
        s[i * 66] = 0.f;            // left col
        s[i * 66 + 65] = 0.f;       // right col
    }
    __syncthreads();
    // interior fill, float4
    const float4* ip4 = reinterpret_cast<const float4*>(ip);
#pragma unroll
    for (int t = 0; t < 4; t++) {
        int i = tid + t * 256;            // 0..1023 float4s
        int x = i >> 4, y4 = (i & 15) * 4;
        float4 v = ip4[i];
        float* d = &s[(x + 1) * 66 + y4 + 1];
        d[0] = v.x; d[1] = v.y; d[2] = v.z; d[3] = v.w;
    }
    __syncthreads();

    float r[16];
#pragma unroll
    for (int t = 0; t < 16; t++) {
        int i = tid + t * 256;
        int x = i >> 6, y = i & 63;
        const float* c = &s[(x + 1) * 66 + (y + 1)];
        r[t] = c[-67] * w0 + c[-66] * w1 + c[-65] * w2
             + c[-1]  * w3 + c[0]   * w4 + c[1]   * w5
             + c[65]  * w6 + c[66]  * w7 + c[67]  * w8;
    }

    if (!is_k) {
#pragma unroll
        for (int t = 0; t < 16; t++) op[tid + t * 256] = r[t];
        return;
    }

    // fused sequence softmax (4096 values across the block)
    float m = -1e30f;
#pragma unroll
    for (int t = 0; t < 16; t++) m = fmaxf(m, r[t]);
#pragma unroll
    for (int o = 16; o; o >>= 1) m = fmaxf(m, __shfl_xor_sync(~0u, m, o));
    if ((tid & 31) == 0) red[tid >> 5] = m;
    __syncthreads();
    m = red[0];
#pragma unroll
    for (int w = 1; w < 8; w++) m = fmaxf(m, red[w]);

    float ssum = 0.f;
#pragma unroll
    for (int t = 0; t < 16; t++) { r[t] = __expf(r[t] - m); ssum += r[t]; }
#pragma unroll
    for (int o = 16; o; o >>= 1) ssum += __shfl_xor_sync(~0u, ssum, o);
    __syncthreads();
    if ((tid & 31) == 0) red[tid >> 5] = ssum;
    __syncthreads();
    ssum = 0.f;
#pragma unroll
    for (int w = 0; w < 8; w++) ssum += red[w];

    float inv = 1.f / ssum;
#pragma unroll
    for (int t = 0; t < 16; t++) op[tid + t * 256] = r[t] * inv;
}

// =====================================================================
// 4. partial ctx: ctxp[bh][s][d][e] = sum_{p in slice s} k[..p,d]*v[..p,e]
//    grid (128, 4); slice = 1024 pixels
// =====================================================================
__global__ __launch_bounds__(256)
void ctx_part(const float* __restrict__ b2, float* __restrict__ ctxp)
{
    __shared__ float sh[8448];
    float* ksT = sh;
    float* vsT = sh + 4224;

    int bh = blockIdx.x;
    int sl = blockIdx.y;
    int b = bh >> 3, h = bh & 7;
    const float* kb = b2 + ((size_t)b * 768 + 256 + h * DHEAD) * NPIX;
    const float* vb = b2 + ((size_t)b * 768 + 512 + h * DHEAD) * NPIX;

    int tid = threadIdx.x;
    int pg = tid >> 6;
    int t  = tid & 63;
    int d0 = (t >> 3) * 4;
    int e0 = (t & 7) * 4;

    float acc[16];
#pragma unroll
    for (int i = 0; i < 16; i++) acc[i] = 0.f;

    int base = sl * 1024;
    for (int c0 = base; c0 < base + 1024; c0 += 128) {
        __syncthreads();
        for (int i = tid; i < 4096; i += 256) {
            int d = i >> 7, p = i & 127;
            ksT[p * 33 + d] = kb[(size_t)d * NPIX + c0 + p];
            vsT[p * 33 + d] = vb[(size_t)d * NPIX + c0 + p];
        }
        __syncthreads();
        int pbeg = pg * 32;
#pragma unroll 4
        for (int pp = pbeg; pp < pbeg + 32; pp++) {
            float kk[4], vv[4];
#pragma unroll
            for (int i = 0; i < 4; i++) kk[i] = ksT[pp * 33 + d0 + i];
#pragma unroll
            for (int j = 0; j < 4; j++) vv[j] = vsT[pp * 33 + e0 + j];
#pragma unroll
            for (int i = 0; i < 4; i++)
#pragma unroll
                for (int j = 0; j < 4; j++) acc[i * 4 + j] += kk[i] * vv[j];
        }
    }
    __syncthreads();

    float* red = sh;
#pragma unroll
    for (int i = 0; i < 4; i++)
#pragma unroll
        for (int j = 0; j < 4; j++)
            red[pg * 1024 + (d0 + i) * 32 + (e0 + j)] = acc[i * 4 + j];
    __syncthreads();

    float* cout = ctxp + (size_t)bh * 4096 + sl * 1024;
    for (int i = tid; i < 1024; i += 256)
        cout[i] = red[i] + red[1024 + i] + red[2048 + i] + red[3072 + i];
}

// =====================================================================
// 5. attn_out: q feature-softmax*SCALE + q@ctx + SiLU -> pixel-major fp16
// =====================================================================
__global__ __launch_bounds__(256)
void attn_out_kernel(const float* __restrict__ qbuf, const float* __restrict__ ctxp,
                     __half* __restrict__ out)
{
    __shared__ float cs[DHEAD][DHEAD + 1];
    int blk = blockIdx.x;
    int pt = blk & 15;
    int bh = blk >> 4;
    int b = bh >> 3, h = bh & 7;

    const float* cbase = ctxp + (size_t)bh * 4096;
    for (int i = threadIdx.x; i < 1024; i += 256)
        cs[i >> 5][i & 31] = cbase[i] + cbase[1024 + i] + cbase[2048 + i] + cbase[3072 + i];
    __syncthreads();

    int p = pt * 256 + threadIdx.x;
    const float* qb = qbuf + ((size_t)b * 768 + h * DHEAD) * NPIX + p;

    float qv[DHEAD];
    float m = -1e30f;
#pragma unroll
    for (int d = 0; d < DHEAD; d++) { qv[d] = qb[(size_t)d * NPIX]; m = fmaxf(m, qv[d]); }
    float ssum = 0.f;
#pragma unroll
    for (int d = 0; d < DHEAD; d++) { qv[d] = __expf(qv[d] - m); ssum += qv[d]; }
    float qinv = SCALE / ssum;

    float o[DHEAD];
#pragma unroll
    for (int e = 0; e < DHEAD; e++) o[e] = 0.f;
#pragma unroll 8
    for (int d = 0; d < DHEAD; d++) {
        float qd = qv[d] * qinv;
#pragma unroll
        for (int e = 0; e < DHEAD; e++) o[e] += qd * cs[d][e];
    }

    __half* ob = out + ((size_t)b * NPIX + p) * DIM + h * DHEAD;
#pragma unroll
    for (int e8 = 0; e8 < DHEAD; e8 += 8) {
        __half2 hh[4];
#pragma unroll
        for (int j = 0; j < 4; j++) {
            float x0 = o[e8 + 2*j],     s0 = x0 / (1.f + __expf(-x0));
            float x1 = o[e8 + 2*j + 1], s1 = x1 / (1.f + __expf(-x1));
            hh[j] = __floats2half2_rn(s0, s1);
        }
        *reinterpret_cast<uint4*>(ob + e8) = *reinterpret_cast<uint4*>(hh);
    }
}

// =====================================================================
// 6. wo GEMM (M=256 full, N=64, K=256) + fused channel LayerNorm -> d_out
//    512 threads: warp grid 8x2, each warp 32x32 (2x2 fp16 frags)
// =====================================================================
#define WOK 32
#define WOLD (WOK + 8)
#define WO_PIPE_BYTES ((256 * WOLD + 64 * WOLD) * 2 * 2)      /* 51200 */
#define WO_EP_BYTES   (256 * 68 * 4)                          /* 69632 */
#define WO_DYN (WO_EP_BYTES > WO_PIPE_BYTES ? WO_EP_BYTES : WO_PIPE_BYTES)

__global__ __launch_bounds__(512)
void gemm_wo_ln(const __half* __restrict__ A, const __half* __restrict__ B,
                const float* __restrict__ gout, float* __restrict__ out)
{
    extern __shared__ char dyn[];
    typedef __half AsT[256][WOLD];
    typedef __half BsT[64][WOLD];
    AsT* As = (AsT*)dyn;                                  // As[2]
    BsT* Bs = (BsT*)(dyn + 2 * 256 * WOLD * 2);           // Bs[2]
    float (*ep)[68] = (float (*)[68])dyn;                 // epilogue reuse

    __shared__ float red1[8][64], red2[8][64];
    __shared__ float smean[64], srstd[64];

    const int tid = threadIdx.x;
    const int bn = blockIdx.x * 64;
    const int z  = blockIdx.z;
    const __half* Bb = B + (size_t)z * NPIX * DIM;

    const int warp = tid >> 5;
    const int wm = (warp >> 1) * 32;
    const int wn = (warp & 1) * 32;

    // A loads: 256 rows x 32 cols per chunk; thread -> 2 rows
    const int ar  = tid >> 2;             // 0..127
    const int ac8 = (tid & 3) * 8;
    const __half* gA0 = &A[(size_t)ar * 256 + ac8];
    const __half* gA1 = &A[(size_t)(ar + 128) * 256 + ac8];
    // B loads: 64 rows x 32 cols; first 256 threads
    const __half* gB = &Bb[(size_t)(bn + (tid >> 2)) * 256 + ac8];

    wmma::fragment<wmma::accumulator, 16, 16, 16, float> acc[2][2];
#pragma unroll
    for (int i = 0; i < 2; i++)
#pragma unroll
        for (int j = 0; j < 2; j++) wmma::fill_fragment(acc[i][j], 0.f);

    cp16s(&(*As)[ar][ac8],       gA0);
    cp16s(&(*As)[ar + 128][ac8], gA1);
    if (tid < 256) cp16s(&(*Bs)[tid >> 2][ac8], gB);
    CP_COMMIT();

    int buf = 0;
#pragma unroll 1
    for (int t = 0; t < 8; t++) {
        CP_WAIT0();
        __syncthreads();
        if (t < 7) {
            int k0 = (t + 1) * WOK;
            cp16s(&As[buf ^ 1][0][0] + (size_t)ar * WOLD + ac8,         gA0 + k0);
            cp16s(&As[buf ^ 1][0][0] + (size_t)(ar + 128) * WOLD + ac8, gA1 + k0);
            if (tid < 256)
                cp16s(&Bs[buf ^ 1][0][0] + (size_t)(tid >> 2) * WOLD + ac8, gB + k0);
            CP_COMMIT();
        }
#pragma unroll
        for (int kk = 0; kk < WOK; kk += 16) {
            wmma::fragment<wmma::matrix_a, 16, 16, 16, __half, wmma::row_major> af[2];
            wmma::fragment<wmma::matrix_b, 16, 16, 16, __half, wmma::col_major> bf[2];
#pragma unroll
            for (int i = 0; i < 2; i++)
                wmma::load_matrix_sync(af[i], &As[buf][0][0] + (size_t)(wm + i * 16) * WOLD + kk, WOLD);
#pragma unroll
            for (int j = 0; j < 2; j++)
                wmma::load_matrix_sync(bf[j], &Bs[buf][0][0] + (size_t)(wn + j * 16) * WOLD + kk, WOLD);
#pragma unroll
            for (int i = 0; i < 2; i++)
#pragma unroll
                for (int j = 0; j < 2; j++)
                    wmma::mma_sync(acc[i][j], af[i], bf[j], acc[i][j]);
        }
        buf ^= 1;
    }

    __syncthreads();   // pipeline smem dead; reuse as epilogue buffer
#pragma unroll
    for (int i = 0; i < 2; i++)
#pragma unroll
        for (int j = 0; j < 2; j++)
            wmma::store_matrix_sync(&ep[wm + i * 16][wn + j * 16], acc[i][j], 68,
                                    wmma::mem_row_major);
    __syncthreads();

    // column (pixel) LayerNorm stats over 256 channels
    {
        int col = tid & 63, part = tid >> 6;     // 8 parts x 32 rows
        float s = 0.f, ss = 0.f;
#pragma unroll 8
        for (int rI = part * 32; rI < part * 32 + 32; rI++) {
            float v = ep[rI][col];
            s += v; ss += v * v;
        }
        red1[part][col] = s;
        red2[part][col] = ss;
    }
    __syncthreads();
    if (tid < 64) {
        float s = 0.f, ss = 0.f;
#pragma unroll
        for (int pI = 0; pI < 8; pI++) { s += red1[pI][tid]; ss += red2[pI][tid]; }
        float mean = s * (1.f / 256.f);
        float var  = ss * (1.f / 256.f) - mean * mean;
        smean[tid] = mean;
        srstd[tid] = rsqrtf(var + EPS);
    }
    __syncthreads();

    float* ob = out + (size_t)z * DIM * NPIX + bn;
    for (int idx = tid; idx < 256 * 64; idx += 512) {
        int c = idx >> 6, p = idx & 63;
        ob[(size_t)c * NPIX + p] = (ep[c][p] - smean[p]) * srstd[p] * __ldg(&gout[c]);
    }
}

// =====================================================================
// launch
// =====================================================================
extern "C" void kernel_launch(void* const* d_in, const int* in_sizes, int n_in,
                              void* d_out, int out_size)
{
    const float* fmap   = (const float*)d_in[0];
    const float* gn     = (const float*)d_in[1];
    const float* wq1    = (const float*)d_in[2];
    const float* wq_dw  = (const float*)d_in[3];
    const float* wk1    = (const float*)d_in[4];
    const float* wk_dw  = (const float*)d_in[5];
    const float* wv1    = (const float*)d_in[6];
    const float* wv_dw  = (const float*)d_in[7];
    const float* wo     = (const float*)d_in[8];
    const float* gout   = (const float*)d_in[9];
    float* out = (float*)d_out;

    __half *xnh, *wqkv, *wo2;
    float *b1, *b2, *ctxp;
    cudaGetSymbolAddress((void**)&xnh,  g_xnh);
    cudaGetSymbolAddress((void**)&b1,   g_b1);
    cudaGetSymbolAddress((void**)&b2,   g_b2);
    cudaGetSymbolAddress((void**)&ctxp, g_ctxp);
    cudaGetSymbolAddress((void**)&wqkv, g_wqkv);
    cudaGetSymbolAddress((void**)&wo2,  g_wo2);

    cudaFuncSetAttribute(gemm_wo_ln, cudaFuncAttributeMaxDynamicSharedMemorySize, WO_DYN);

    // 0. weights -> fp16
    round_weights<<<768, 256>>>(wq1, wk1, wv1, wo);

    // 1. channel LN -> pixel-major fp16
    ln_to_pix<<<256, 256>>>(fmap, gn, xnh);

    // 2. fused QKV 1x1 conv (fp16 WMMA)
    gemm_fp16<<<dim3(NPIX / BN, 768 / BM, BATCH), 512>>>(
        wqkv, xnh, b1, (long)NPIX * DIM, 768L * NPIX);

    // 3. depthwise 3x3 all channels (+ fused k sequence-softmax)
    dwconv_all<<<BATCH * 768, 256>>>(b1, wq_dw, wk_dw, wv_dw, b2);

    // 4. partial ctx = k^T v (4 pixel slices)
    ctx_part<<<dim3(BATCH * HEADS, 4), 256>>>(b2, ctxp);

    // 5. attn out: q softmax + q@ctx + SiLU -> pixel-major fp16
    attn_out_kernel<<<2048, 256>>>(b2, ctxp, xnh);

    // 6. wo GEMM + fused final LayerNorm -> d_out
    gemm_wo_ln<<<dim3(NPIX / 64, 1, BATCH), 512, WO_DYN>>>(wo2, xnh, gout, out);
}